// round 1
// baseline (speedup 1.0000x reference)
#include <cuda_runtime.h>
#include <cstdint>
#include <cstddef>

// Problem constants (B=8, S=24, N=4096, K=9, C1=32, C2=16)
#define BS_TOT 192
#define SDIM   24
#define NPTS   4096
#define KNB    9
#define C1V    32
#define C2V    16
#define JTOT   36864   // KNB * NPTS
#define BN_EPS 1e-5f

// ---------------- device scratch (static globals: allocation-free) ----------
__device__ unsigned short d_P[JTOT];            // flattened gather permutation
__device__ float g_sum[SDIM * C2V];
__device__ float g_sumsq[SDIM * C2V];
__device__ float g_A[SDIM * C2V];
__device__ float g_B[SDIM * C2V];
__device__ float g_h[(size_t)BS_TOT * C1V * NPTS];   // stage-1 output  (96 MB)
__device__ float g_y2[(size_t)BS_TOT * C2V * NPTS];  // stage-2 output  (48 MB)

// ---------------- packed f32x2 helpers (sm_103a FFMA2 path) ----------------
__device__ __forceinline__ unsigned long long pack2(float x, float y) {
    unsigned long long r;
    asm("mov.b64 %0, {%1, %2};" : "=l"(r)
        : "r"(__float_as_uint(x)), "r"(__float_as_uint(y)));
    return r;
}
__device__ __forceinline__ float2 unpack2(unsigned long long v) {
    unsigned int a, b;
    asm("mov.b64 {%0, %1}, %2;" : "=r"(a), "=r"(b) : "l"(v));
    return make_float2(__uint_as_float(a), __uint_as_float(b));
}
#define FMA2(acc, a, b) \
    asm("fma.rn.f32x2 %0, %1, %2, %0;" : "+l"(acc) : "l"(a), "l"(b))

// ---------------- K0: build permutation + zero BN accumulators -------------
__global__ void k0_prep(const int* __restrict__ neigh) {
    int j = blockIdx.x * 256 + threadIdx.x;
    if (j < JTOT) {
        int n = j & (NPTS - 1);
        int k = j >> 12;
        d_P[j] = (unsigned short)neigh[n * KNB + k];
    }
    if (j < SDIM * C2V) { g_sum[j] = 0.f; g_sumsq[j] = 0.f; }
}

// ---------------- K1: stage 1 (9-tap conv, C1=32 outputs) ------------------
__global__ void __launch_bounds__(256) k1_stage1(
    const float* __restrict__ in, const float* __restrict__ W1,
    const float* __restrict__ b1)
{
    __shared__ __align__(16) unsigned long long sw[KNB * 16];  // [q][oh] pairs
    __shared__ unsigned long long sb[16];
    int t = threadIdx.x;
    if (t < KNB * 16) {
        int q = t >> 4, oh = t & 15;
        sw[t] = pack2(W1[(2 * oh) * KNB + q], W1[(2 * oh + 1) * KNB + q]);
    }
    if (t < 16) sb[t] = pack2(b1[2 * t], b1[2 * t + 1]);
    __syncthreads();

    int g  = blockIdx.x * 256 + t;
    int bs = g >> 12;
    int pp = g & (NPTS - 1);
    const float* ip = in + (size_t)bs * JTOT;

    unsigned long long acc[16];
#pragma unroll
    for (int oh = 0; oh < 16; oh++) acc[oh] = sb[oh];

    int base = pp * KNB;
#pragma unroll
    for (int q = 0; q < KNB; q++) {
        int jt = base + q;
        int n  = jt & (NPTS - 1);
        int k  = jt >> 12;
        float v = __ldg(ip + n * KNB + k);
        unsigned long long v2 = pack2(v, v);
        const ulonglong2* w = (const ulonglong2*)(sw + q * 16);
#pragma unroll
        for (int oh2 = 0; oh2 < 8; oh2++) {
            ulonglong2 ww = w[oh2];
            FMA2(acc[2 * oh2],     v2, ww.x);
            FMA2(acc[2 * oh2 + 1], v2, ww.y);
        }
    }

    float* hp = g_h + (size_t)bs * (C1V * NPTS) + pp;
#pragma unroll
    for (int oh = 0; oh < 16; oh++) {
        float2 f = unpack2(acc[oh]);
        hp[(2 * oh) * NPTS]     = fmaxf(f.x, 0.f);
        hp[(2 * oh + 1) * NPTS] = fmaxf(f.y, 0.f);
    }
}

// ---------------- K2: stage 2 (gather + 128x16x288 GEMM) + BN stats --------
__global__ void __launch_bounds__(128) k2_stage2(
    const float* __restrict__ W2, const float* __restrict__ b2)
{
    __shared__ float sh_h[NPTS];                                 // 16 KB
    __shared__ __align__(16) unsigned long long sh_w[288 * 8];   // 18 KB pairs
    __shared__ float red_s[4][16];
    __shared__ float red_q[4][16];

    int blk = blockIdx.x;
    int bs  = blk >> 5;
    int c   = blk & 31;
    int t   = threadIdx.x;   // 128 threads, one output row p' each

    const float4* hsrc = (const float4*)(g_h + ((size_t)bs * C1V + c) * NPTS);
    float4* hdst = (float4*)sh_h;
    for (int i = t; i < NPTS / 4; i += 128) hdst[i] = hsrc[i];
    for (int i = t; i < 288 * 8; i += 128) {
        int q = i >> 3, oh = i & 7;
        sh_w[i] = pack2(W2[(2 * oh) * 288 + q], W2[(2 * oh + 1) * 288 + q]);
    }
    __syncthreads();

    unsigned long long acc[8];
#pragma unroll
    for (int oh = 0; oh < 8; oh++)
        acc[oh] = pack2(__ldg(b2 + 2 * oh), __ldg(b2 + 2 * oh + 1));

    // this thread's 288 gather indices: d_P[t*288 .. ), as uint4 (8 u16 each)
    const uint4* Pp = (const uint4*)(d_P) + t * 36;
#pragma unroll 2
    for (int q8 = 0; q8 < 36; q8++) {
        uint4 pv = Pp[q8];
        unsigned idx[8] = { pv.x & 0xFFFFu, pv.x >> 16,
                            pv.y & 0xFFFFu, pv.y >> 16,
                            pv.z & 0xFFFFu, pv.z >> 16,
                            pv.w & 0xFFFFu, pv.w >> 16 };
#pragma unroll
        for (int j = 0; j < 8; j++) {
            float hv = sh_h[idx[j]];
            unsigned long long h2 = pack2(hv, hv);
            const ulonglong2* w = (const ulonglong2*)(sh_w + (q8 * 8 + j) * 8);
#pragma unroll
            for (int oh2 = 0; oh2 < 4; oh2++) {
                ulonglong2 ww = w[oh2];
                FMA2(acc[2 * oh2],     h2, ww.x);
                FMA2(acc[2 * oh2 + 1], h2, ww.y);
            }
        }
    }

    float y[16];
#pragma unroll
    for (int oh = 0; oh < 8; oh++) {
        float2 f = unpack2(acc[oh]);
        y[2 * oh] = f.x; y[2 * oh + 1] = f.y;
    }

    float* dst = g_y2 + (size_t)bs * (C2V * NPTS) + c * 128 + t;
#pragma unroll
    for (int o = 0; o < 16; o++) dst[o * NPTS] = y[o];

    // BN partial sums: reduce 128 p' within the block, atomically merge
    int warp = t >> 5, lane = t & 31;
#pragma unroll
    for (int o = 0; o < 16; o++) {
        float v = y[o], sq = y[o] * y[o];
#pragma unroll
        for (int off = 16; off; off >>= 1) {
            v  += __shfl_down_sync(0xFFFFFFFFu, v,  off);
            sq += __shfl_down_sync(0xFFFFFFFFu, sq, off);
        }
        if (lane == 0) { red_s[warp][o] = v; red_q[warp][o] = sq; }
    }
    __syncthreads();
    if (t < 16) {
        float a = red_s[0][t] + red_s[1][t] + red_s[2][t] + red_s[3][t];
        float q = red_q[0][t] + red_q[1][t] + red_q[2][t] + red_q[3][t];
        int s = bs % SDIM;
        atomicAdd(&g_sum[s * C2V + t], a);
        atomicAdd(&g_sumsq[s * C2V + t], q);
    }
}

// ---------------- K2b: finalize BN scale/shift per (s, o) ------------------
__global__ void k2b_bnfinal(const float* __restrict__ gamma,
                            const float* __restrict__ beta)
{
    int i = threadIdx.x;
    if (i < SDIM * C2V) {
        const float cnt = 8.0f * (float)NPTS;   // B * N = 32768
        float mean = g_sum[i] / cnt;
        float var  = g_sumsq[i] / cnt - mean * mean;
        int o = i & 15;
        float A = gamma[o] * rsqrtf(var + BN_EPS);
        g_A[i] = A;
        g_B[i] = beta[o] - mean * A;
    }
}

// ---------------- K3: BN apply + relu + gather + 144-dot + relu ------------
__global__ void __launch_bounds__(256) k3_stage3(
    const float* __restrict__ W3, const float* __restrict__ b3,
    float* __restrict__ out)
{
    __shared__ float shv[NPTS];     // normalized+relu'd channel slice
    __shared__ float sw3[144];

    int blk = blockIdx.x;
    int bs  = blk >> 4;
    int c   = blk & 15;
    int t   = threadIdx.x;   // 256 threads, one output p' each
    int s   = bs % SDIM;

    float A  = g_A[s * C2V + c];
    float Bc = g_B[s * C2V + c];

    const float4* src = (const float4*)(g_y2 + ((size_t)bs * C2V + c) * NPTS);
    for (int i = t; i < NPTS / 4; i += 256) {
        float4 v = src[i];
        shv[4 * i + 0] = fmaxf(fmaf(v.x, A, Bc), 0.f);
        shv[4 * i + 1] = fmaxf(fmaf(v.y, A, Bc), 0.f);
        shv[4 * i + 2] = fmaxf(fmaf(v.z, A, Bc), 0.f);
        shv[4 * i + 3] = fmaxf(fmaf(v.w, A, Bc), 0.f);
    }
    if (t < 144) sw3[t] = W3[t];
    __syncthreads();

    float acc = __ldg(b3);
    const uint4* Pp = (const uint4*)(d_P) + t * 18;  // 144 u16 = 18 uint4
#pragma unroll
    for (int q8 = 0; q8 < 18; q8++) {
        uint4 pv = Pp[q8];
        unsigned idx[8] = { pv.x & 0xFFFFu, pv.x >> 16,
                            pv.y & 0xFFFFu, pv.y >> 16,
                            pv.z & 0xFFFFu, pv.z >> 16,
                            pv.w & 0xFFFFu, pv.w >> 16 };
#pragma unroll
        for (int j = 0; j < 8; j++)
            acc = fmaf(shv[idx[j]], sw3[q8 * 8 + j], acc);
    }
    out[(size_t)bs * NPTS + c * 256 + t] = fmaxf(acc, 0.f);
}

// ---------------- launch -----------------------------------------------------
extern "C" void kernel_launch(void* const* d_in, const int* in_sizes, int n_in,
                              void* d_out, int out_size)
{
    const float* input = (const float*)d_in[0];
    const int*   neigh = (const int*)  d_in[1];
    const float* W1    = (const float*)d_in[2];
    const float* b1    = (const float*)d_in[3];
    const float* W2    = (const float*)d_in[4];
    const float* b2    = (const float*)d_in[5];
    const float* gamma = (const float*)d_in[6];
    const float* beta  = (const float*)d_in[7];
    const float* W3    = (const float*)d_in[8];
    const float* b3    = (const float*)d_in[9];
    float* out = (float*)d_out;

    k0_prep<<<144, 256>>>(neigh);
    k1_stage1<<<(BS_TOT * NPTS) / 256, 256>>>(input, W1, b1);
    k2_stage2<<<BS_TOT * C1V, 128>>>(W2, b2);
    k2b_bnfinal<<<1, 384>>>(gamma, beta);
    k3_stage3<<<BS_TOT * C2V, 256>>>(W3, b3, out);
}